// round 14
// baseline (speedup 1.0000x reference)
#include <cuda_runtime.h>
#include <cuda_bf16.h>
#include <cstdint>
#include <cstddef>

// ============================================================================
// Problem constants
// ============================================================================
namespace cfg {
constexpr int B = 4, T = 512, H = 2048, V = 32000;
constexpr int M = B * T;                 // 2048 tokens
constexpr float BETA = 0.1f;

// GEMM tiling (Ampere-style mma.sync path — tcgen05 not accepted by this
// toolchain's compute_103 target)
constexpr int BM = 128;                  // CTA M tile
constexpr int BN = 256;                  // CTA N tile
constexpr int BK = 64;                   // K block (64 bf16 = 128B = SW128 atom row)
constexpr int KITERS = H / BK;           // 32
constexpr int STAGES = 3;
constexpr int NCHUNK = V / BN;           // 125
static_assert(NCHUNK * BN == V, "vocab tiling");

// SMEM: per stage A(128x128B)=16KB + B(256x128B)=32KB; 3 stages + epilogue
constexpr int ASZ = BM * 128;            // 16384
constexpr int BSZ = BN * 128;            // 32768
constexpr int STG = ASZ + BSZ;           // 49152
constexpr int EPI_OFF = STAGES * STG;    // 147456
constexpr int SMEM_TOTAL = EPI_OFF + 4 * BM * 2 * 4;  // +4KB epi = 151552
}  // namespace cfg

// ============================================================================
// Persistent device scratch (no runtime allocation allowed)
// ============================================================================
__device__ __nv_bfloat16 g_wb[2][(size_t)cfg::V * cfg::H];   // bf16 weights
__device__ __nv_bfloat16 g_xb[2][(size_t)cfg::M * cfg::H];   // bf16 activations
__device__ float g_seldot[2 * cfg::M];                       // exact fp32 selected logits
__device__ float g_part[2 * cfg::NCHUNK * 2 * cfg::M];       // per-chunk (max, sumexp)
__device__ float g_bsum[16];                                 // block partial sums

// ============================================================================
// PTX helpers
// ============================================================================
__device__ __forceinline__ uint32_t smem_u32(const void* p) {
    uint32_t a;
    asm("{ .reg .u64 t; cvta.to.shared.u64 t, %1; cvt.u32.u64 %0, t; }"
        : "=r"(a) : "l"(p));
    return a;
}

// cp.async 16B
#define CP_ASYNC16(dst_u32, src_ptr) \
    asm volatile("cp.async.cg.shared.global [%0], [%1], 16;" \
                 :: "r"(dst_u32), "l"(src_ptr) : "memory")
#define CP_COMMIT() asm volatile("cp.async.commit_group;" ::: "memory")
#define CP_WAIT2()  asm volatile("cp.async.wait_group 2;" ::: "memory")
#define CP_WAIT0()  asm volatile("cp.async.wait_group 0;" ::: "memory")

__device__ __forceinline__ uint32_t sw128(uint32_t off) {
    return off ^ ((off >> 3) & 0x70);
}

__device__ __forceinline__ void ldsm4(uint32_t* r, uint32_t addr) {
    asm volatile("ldmatrix.sync.aligned.m8n8.x4.shared.b16 {%0,%1,%2,%3}, [%4];"
                 : "=r"(r[0]), "=r"(r[1]), "=r"(r[2]), "=r"(r[3]) : "r"(addr));
}

__device__ __forceinline__ void mma16816(float* c, const uint32_t* a,
                                         uint32_t b0, uint32_t b1) {
    asm volatile(
        "mma.sync.aligned.m16n8k16.row.col.f32.bf16.bf16.f32 "
        "{%0,%1,%2,%3}, {%4,%5,%6,%7}, {%8,%9}, {%0,%1,%2,%3};"
        : "+f"(c[0]), "+f"(c[1]), "+f"(c[2]), "+f"(c[3])
        : "r"(a[0]), "r"(a[1]), "r"(a[2]), "r"(a[3]), "r"(b0), "r"(b1));
}

// ============================================================================
// Kernel 1: fp32 -> bf16 conversion
// ============================================================================
__global__ void k_convert(const float4* __restrict__ src, int target, long long n4) {
    __nv_bfloat162* dst =
        target == 0 ? (__nv_bfloat162*)g_wb[0] :
        target == 1 ? (__nv_bfloat162*)g_wb[1] :
        target == 2 ? (__nv_bfloat162*)g_xb[0] : (__nv_bfloat162*)g_xb[1];
    long long stride = (long long)gridDim.x * blockDim.x;
    for (long long i = (long long)blockIdx.x * blockDim.x + threadIdx.x; i < n4; i += stride) {
        float4 v = src[i];
        dst[2 * i]     = __float22bfloat162_rn(make_float2(v.x, v.y));
        dst[2 * i + 1] = __float22bfloat162_rn(make_float2(v.z, v.w));
    }
}

// ============================================================================
// Kernel 2: exact fp32 selected-token logits (one warp per (gemm, token))
// ============================================================================
__global__ void k_seldot(const float* __restrict__ x0, const float* __restrict__ w0,
                         const float* __restrict__ x1, const float* __restrict__ w1,
                         const int* __restrict__ ids) {
    int wglob = (blockIdx.x * blockDim.x + threadIdx.x) >> 5;
    int lane  = threadIdx.x & 31;
    int g = wglob >> 11;          // /2048
    int m = wglob & (cfg::M - 1);
    if (g >= 2) return;
    const float* x = g ? x1 : x0;
    const float* w = g ? w1 : w0;
    int sel = ids[m];
    const float* xr = x + (size_t)m * cfg::H;
    const float* wr = w + (size_t)sel * cfg::H;
    float acc = 0.f;
    #pragma unroll 8
    for (int k = lane; k < cfg::H; k += 32) acc = fmaf(xr[k], wr[k], acc);
    #pragma unroll
    for (int o = 16; o; o >>= 1) acc += __shfl_xor_sync(0xffffffffu, acc, o);
    if (lane == 0) g_seldot[g * cfg::M + m] = acc;
}

// ============================================================================
// Kernel 3: bf16 mma.sync GEMM + streaming logsumexp partials
//   grid = (16 m-tiles, 125 v-chunks, 2 gemms), 256 threads (8 warps)
//   warp grid 2(M) x 4(N), warp tile 64x64
// ============================================================================
__device__ __forceinline__ void load_tile_A(uint32_t smem_abs, const __nv_bfloat16* __restrict__ X,
                                            int m_base, int k0, int tid) {
    // 128 rows x 128B (64 bf16), 1024 x 16B chunks, 256 threads -> 4 iters
    #pragma unroll
    for (int i = 0; i < 4; i++) {
        int idx = tid + i * 256;
        int row = idx >> 3, c16 = idx & 7;
        uint32_t boff = (uint32_t)row * 128u + (uint32_t)c16 * 16u;
        const void* g = X + (size_t)(m_base + row) * cfg::H + k0 + c16 * 8;
        CP_ASYNC16(smem_abs + sw128(boff), g);
    }
}

__device__ __forceinline__ void load_tile_B(uint32_t smem_abs, const __nv_bfloat16* __restrict__ W,
                                            int v_base, int k0, int tid) {
    // 256 rows x 128B, 2048 x 16B chunks, 256 threads -> 8 iters
    #pragma unroll
    for (int i = 0; i < 8; i++) {
        int idx = tid + i * 256;
        int row = idx >> 3, c16 = idx & 7;
        uint32_t boff = (uint32_t)row * 128u + (uint32_t)c16 * 16u;
        const void* g = W + (size_t)(v_base + row) * cfg::H + k0 + c16 * 8;
        CP_ASYNC16(smem_abs + sw128(boff), g);
    }
}

__global__ void __launch_bounds__(256) k_lse() {
    extern __shared__ char smem[];
    const uint32_t sb = smem_u32(smem);
    const int tid  = threadIdx.x;
    const int lane = tid & 31;
    const int warp = tid >> 5;
    const int wm = warp & 1;          // 2 M-warps x 64
    const int wn = warp >> 1;         // 4 N-warps x 64
    const int g = blockIdx.z;
    const int m_base = blockIdx.x * cfg::BM;
    const int v_base = blockIdx.y * cfg::BN;
    const __nv_bfloat16* X = g_xb[g];
    const __nv_bfloat16* W = g_wb[g];

    // ldmatrix lane address patterns
    const int a_row = wm * 64 + (lane & 15);          // + mt*16
    const int a_hi  = (lane >> 4) * 16;               // 0 / 16 byte chunk
    const int b_row = wn * 64 + (lane & 7) + ((lane >> 4) << 3);  // + ntt*16
    const int b_hi  = ((lane >> 3) & 1) * 16;

    float c[4][8][4];
    #pragma unroll
    for (int mt = 0; mt < 4; mt++)
        #pragma unroll
        for (int nt = 0; nt < 8; nt++)
            #pragma unroll
            for (int j = 0; j < 4; j++) c[mt][nt][j] = 0.f;

    // Prologue: fill STAGES-1.. actually fill all 3 stages
    #pragma unroll
    for (int s = 0; s < cfg::STAGES; s++) {
        load_tile_A(sb + s * cfg::STG, X, m_base, s * cfg::BK, tid);
        load_tile_B(sb + s * cfg::STG + cfg::ASZ, W, v_base, s * cfg::BK, tid);
        CP_COMMIT();
    }

    for (int kb = 0; kb < cfg::KITERS; ++kb) {
        // group kb complete when <=2 pending (groups kb..kb+2 committed so far)
        if (kb < cfg::KITERS - 2) { CP_WAIT2(); } else { CP_WAIT0(); }
        __syncthreads();

        const uint32_t stg = sb + (kb % cfg::STAGES) * cfg::STG;
        const uint32_t aB = stg, bB = stg + cfg::ASZ;

        #pragma unroll
        for (int s = 0; s < 4; s++) {   // 4 x k16 within BK=64
            uint32_t af[4][4], bf[4][4];
            #pragma unroll
            for (int mt = 0; mt < 4; mt++)
                ldsm4(af[mt], aB + sw128((uint32_t)(a_row + mt * 16) * 128u + s * 32 + a_hi));
            #pragma unroll
            for (int ntt = 0; ntt < 4; ntt++)
                ldsm4(bf[ntt], bB + sw128((uint32_t)(b_row + ntt * 16) * 128u + s * 32 + b_hi));
            #pragma unroll
            for (int mt = 0; mt < 4; mt++)
                #pragma unroll
                for (int nt = 0; nt < 8; nt++)
                    mma16816(c[mt][nt], af[mt], bf[nt >> 1][(nt & 1) * 2],
                             bf[nt >> 1][(nt & 1) * 2 + 1]);
        }
        __syncthreads();   // mainloop reads done before refill overwrites this stage

        if (kb + cfg::STAGES < cfg::KITERS) {
            const int ks = kb + cfg::STAGES;
            const uint32_t ns = sb + (ks % cfg::STAGES) * cfg::STG;
            load_tile_A(ns, X, m_base, ks * cfg::BK, tid);
            load_tile_B(ns + cfg::ASZ, W, v_base, ks * cfg::BK, tid);
            CP_COMMIT();
        }
    }

    // ---- Epilogue: per-row online (max, sumexp) ----
    // C frag: reg0 (r=lane/4, n=2q), reg1 (r, n+1), reg2 (r+8, n), reg3 (r+8, n+1)
    float2* sepi = (float2*)(smem + cfg::EPI_OFF);   // [4 wn][128 rows]
    #pragma unroll
    for (int mt = 0; mt < 4; mt++) {
        #pragma unroll
        for (int h = 0; h < 2; h++) {                // row lo (regs 0,1) / hi (2,3)
            float mx = c[mt][0][2 * h];
            #pragma unroll
            for (int nt = 0; nt < 8; nt++) {
                mx = fmaxf(mx, c[mt][nt][2 * h]);
                mx = fmaxf(mx, c[mt][nt][2 * h + 1]);
            }
            float sum = 0.f;
            #pragma unroll
            for (int nt = 0; nt < 8; nt++) {
                sum += __expf(c[mt][nt][2 * h] - mx);
                sum += __expf(c[mt][nt][2 * h + 1] - mx);
            }
            // quad combine (threads lane^1, lane^2 share the same row)
            #pragma unroll
            for (int off = 1; off <= 2; off <<= 1) {
                float om = __shfl_xor_sync(0xffffffffu, mx, off);
                float ol = __shfl_xor_sync(0xffffffffu, sum, off);
                float nm = fmaxf(mx, om);
                sum = sum * __expf(mx - nm) + ol * __expf(om - nm);
                mx = nm;
            }
            if ((lane & 3) == 0) {
                int row = wm * 64 + mt * 16 + (lane >> 2) + 8 * h;
                sepi[wn * cfg::BM + row] = make_float2(mx, sum);
            }
        }
    }
    __syncthreads();

    if (tid < cfg::BM) {
        float2 p0 = sepi[0 * cfg::BM + tid];
        float mx = p0.x, L = p0.y;
        #pragma unroll
        for (int w = 1; w < 4; w++) {
            float2 p = sepi[w * cfg::BM + tid];
            float nm = fmaxf(mx, p.x);
            L = L * __expf(mx - nm) + p.y * __expf(p.x - nm);
            mx = nm;
        }
        const int gm = m_base + tid;
        const size_t base = ((size_t)(g * cfg::NCHUNK + blockIdx.y) * 2) * cfg::M;
        g_part[base + gm] = mx;
        g_part[base + cfg::M + gm] = L;
    }
}

// ============================================================================
// Kernel 4: merge chunk partials -> per-token loss -> block partial sums
// ============================================================================
__global__ void k_finalize(const float* __restrict__ adv, const int* __restrict__ amask) {
    const int m = blockIdx.x * blockDim.x + threadIdx.x;  // 8 x 256 = 2048
    const float NEG_INF = __int_as_float(0xff800000u);
    float lp[2];
    #pragma unroll
    for (int g = 0; g < 2; ++g) {
        float mx = NEG_INF;
        #pragma unroll 1
        for (int c = 0; c < cfg::NCHUNK; ++c) {
            mx = fmaxf(mx, g_part[((size_t)(g * cfg::NCHUNK + c) * 2) * cfg::M + m]);
        }
        float L = 0.f;
        #pragma unroll 1
        for (int c = 0; c < cfg::NCHUNK; ++c) {
            const size_t base = ((size_t)(g * cfg::NCHUNK + c) * 2) * cfg::M;
            L += g_part[base + cfg::M + m] * __expf(g_part[base + m] - mx);
        }
        lp[g] = g_seldot[g * cfg::M + m] - (mx + logf(L));
    }
    // coef1 = coef2 = 1 exactly -> per-token policy loss = -adv[b]
    const float d  = lp[1] - lp[0];            // ref_logps - logps
    const float kl = expf(d) - d - 1.0f;
    const float mk = (float)amask[m];
    const int b = m / cfg::T;
    const float lt = (-adv[b] + cfg::BETA * kl) * mk;

    __shared__ float sl[256], sm_[256];
    sl[threadIdx.x] = lt;
    sm_[threadIdx.x] = mk;
    __syncthreads();
    for (int o = 128; o; o >>= 1) {
        if (threadIdx.x < o) {
            sl[threadIdx.x] += sl[threadIdx.x + o];
            sm_[threadIdx.x] += sm_[threadIdx.x + o];
        }
        __syncthreads();
    }
    if (threadIdx.x == 0) {
        g_bsum[blockIdx.x] = sl[0];
        g_bsum[8 + blockIdx.x] = sm_[0];
    }
}

__global__ void k_writeout(float* out) {
    if (threadIdx.x == 0) {
        float L = 0.f, Mk = 0.f;
        for (int i = 0; i < 8; i++) { L += g_bsum[i]; Mk += g_bsum[8 + i]; }
        out[0] = L / fmaxf(Mk, 1.0f);
    }
}

// ============================================================================
// Launch
// ============================================================================
extern "C" void kernel_launch(void* const* d_in, const int* in_sizes, int n_in,
                              void* d_out, int out_size) {
    (void)in_sizes; (void)n_in; (void)out_size;
    const float* x   = (const float*)d_in[0];
    const float* lw  = (const float*)d_in[1];
    const float* rx  = (const float*)d_in[2];
    const float* rw  = (const float*)d_in[3];
    const float* adv = (const float*)d_in[4];
    const int*   ids = (const int*)d_in[5];
    const int*   am  = (const int*)d_in[6];

    const long long wh4 = (long long)cfg::V * cfg::H / 4;
    const long long xh4 = (long long)cfg::M * cfg::H / 4;
    k_convert<<<2048, 256>>>((const float4*)lw, 0, wh4);
    k_convert<<<2048, 256>>>((const float4*)rw, 1, wh4);
    k_convert<<<256, 256>>>((const float4*)x,  2, xh4);
    k_convert<<<256, 256>>>((const float4*)rx, 3, xh4);

    k_seldot<<<512, 256>>>(x, lw, rx, rw, ids);

    cudaFuncSetAttribute(k_lse, cudaFuncAttributeMaxDynamicSharedMemorySize, cfg::SMEM_TOTAL);
    dim3 grid(cfg::M / cfg::BM, cfg::NCHUNK, 2);   // (16, 125, 2)
    k_lse<<<grid, 256, cfg::SMEM_TOTAL>>>();

    k_finalize<<<cfg::M / 256, 256>>>(adv, am);
    k_writeout<<<1, 32>>>((float*)d_out);
}

// round 15
// speedup vs baseline: 1.0741x; 1.0741x over previous
#include <cuda_runtime.h>
#include <cuda_bf16.h>
#include <cstdint>
#include <cstddef>

// ============================================================================
// Problem constants
// ============================================================================
namespace cfg {
constexpr int B = 4, T = 512, H = 2048, V = 32000;
constexpr int M = B * T;                 // 2048 tokens
constexpr float BETA = 0.1f;

// GEMM tiling (mma.sync path — tcgen05 rejected by this toolchain's
// compute_103 family target)
constexpr int BM = 128;                  // CTA M tile
constexpr int BN = 256;                  // CTA N tile
constexpr int BK = 64;                   // K block (64 bf16 = 128B = SW128 atom row)
constexpr int KITERS = H / BK;           // 32
constexpr int STAGES = 4;
constexpr int NCHUNK = V / BN;           // 125
static_assert(NCHUNK * BN == V, "vocab tiling");

// SMEM: per stage A(128x128B)=16KB + B(256x128B)=32KB; 4 stages = 192KB.
// Epilogue scratch (4KB) aliases stage 0 (dead after kb=KITERS-4).
constexpr int ASZ = BM * 128;            // 16384
constexpr int BSZ = BN * 128;            // 32768
constexpr int STG = ASZ + BSZ;           // 49152
constexpr int SMEM_TOTAL = STAGES * STG; // 196608
}  // namespace cfg

// ============================================================================
// Persistent device scratch (no runtime allocation allowed)
// ============================================================================
__device__ __nv_bfloat16 g_wb[2][(size_t)cfg::V * cfg::H];   // bf16 weights
__device__ __nv_bfloat16 g_xb[2][(size_t)cfg::M * cfg::H];   // bf16 activations
__device__ float g_seldot[2 * cfg::M];                       // exact fp32 selected logits
__device__ float g_part[2 * cfg::NCHUNK * 2 * cfg::M];       // per-chunk (max, sumexp)
__device__ float g_bsum[16];                                 // block partial sums

// ============================================================================
// PTX helpers
// ============================================================================
__device__ __forceinline__ uint32_t smem_u32(const void* p) {
    uint32_t a;
    asm("{ .reg .u64 t; cvta.to.shared.u64 t, %1; cvt.u32.u64 %0, t; }"
        : "=r"(a) : "l"(p));
    return a;
}

#define CP_ASYNC16(dst_u32, src_ptr) \
    asm volatile("cp.async.cg.shared.global [%0], [%1], 16;" \
                 :: "r"(dst_u32), "l"(src_ptr) : "memory")
#define CP_COMMIT() asm volatile("cp.async.commit_group;" ::: "memory")
#define CP_WAIT2()  asm volatile("cp.async.wait_group 2;" ::: "memory")

__device__ __forceinline__ uint32_t sw128(uint32_t off) {
    return off ^ ((off >> 3) & 0x70);
}

__device__ __forceinline__ void ldsm4(uint32_t* r, uint32_t addr) {
    asm volatile("ldmatrix.sync.aligned.m8n8.x4.shared.b16 {%0,%1,%2,%3}, [%4];"
                 : "=r"(r[0]), "=r"(r[1]), "=r"(r[2]), "=r"(r[3]) : "r"(addr));
}

__device__ __forceinline__ void mma16816(float* c, const uint32_t* a,
                                         uint32_t b0, uint32_t b1) {
    asm volatile(
        "mma.sync.aligned.m16n8k16.row.col.f32.bf16.bf16.f32 "
        "{%0,%1,%2,%3}, {%4,%5,%6,%7}, {%8,%9}, {%0,%1,%2,%3};"
        : "+f"(c[0]), "+f"(c[1]), "+f"(c[2]), "+f"(c[3])
        : "r"(a[0]), "r"(a[1]), "r"(a[2]), "r"(a[3]), "r"(b0), "r"(b1));
}

// ============================================================================
// Kernel 1: fp32 -> bf16 conversion
// ============================================================================
__global__ void k_convert(const float4* __restrict__ src, int target, long long n4) {
    __nv_bfloat162* dst =
        target == 0 ? (__nv_bfloat162*)g_wb[0] :
        target == 1 ? (__nv_bfloat162*)g_wb[1] :
        target == 2 ? (__nv_bfloat162*)g_xb[0] : (__nv_bfloat162*)g_xb[1];
    long long stride = (long long)gridDim.x * blockDim.x;
    for (long long i = (long long)blockIdx.x * blockDim.x + threadIdx.x; i < n4; i += stride) {
        float4 v = src[i];
        dst[2 * i]     = __float22bfloat162_rn(make_float2(v.x, v.y));
        dst[2 * i + 1] = __float22bfloat162_rn(make_float2(v.z, v.w));
    }
}

// ============================================================================
// Kernel 2: exact fp32 selected-token logits (one warp per (gemm, token))
// ============================================================================
__global__ void k_seldot(const float* __restrict__ x0, const float* __restrict__ w0,
                         const float* __restrict__ x1, const float* __restrict__ w1,
                         const int* __restrict__ ids) {
    int wglob = (blockIdx.x * blockDim.x + threadIdx.x) >> 5;
    int lane  = threadIdx.x & 31;
    int g = wglob >> 11;          // /2048
    int m = wglob & (cfg::M - 1);
    if (g >= 2) return;
    const float* x = g ? x1 : x0;
    const float* w = g ? w1 : w0;
    int sel = ids[m];
    const float* xr = x + (size_t)m * cfg::H;
    const float* wr = w + (size_t)sel * cfg::H;
    float acc = 0.f;
    #pragma unroll 8
    for (int k = lane; k < cfg::H; k += 32) acc = fmaf(xr[k], wr[k], acc);
    #pragma unroll
    for (int o = 16; o; o >>= 1) acc += __shfl_xor_sync(0xffffffffu, acc, o);
    if (lane == 0) g_seldot[g * cfg::M + m] = acc;
}

// ============================================================================
// Kernel 3: bf16 mma.sync GEMM + streaming logsumexp partials
//   grid = (16 m-tiles, 125 v-chunks, 2 gemms), 256 threads (8 warps)
//   warp grid 2(M) x 4(N), warp tile 64x64
//   Single-barrier 4-stage cp.async pipeline, double-buffered fragments.
// ============================================================================
__device__ __forceinline__ void load_tile_A(uint32_t smem_abs, const __nv_bfloat16* __restrict__ X,
                                            int m_base, int k0, int tid) {
    #pragma unroll
    for (int i = 0; i < 4; i++) {
        int idx = tid + i * 256;
        int row = idx >> 3, c16 = idx & 7;
        uint32_t boff = (uint32_t)row * 128u + (uint32_t)c16 * 16u;
        const void* g = X + (size_t)(m_base + row) * cfg::H + k0 + c16 * 8;
        CP_ASYNC16(smem_abs + sw128(boff), g);
    }
}

__device__ __forceinline__ void load_tile_B(uint32_t smem_abs, const __nv_bfloat16* __restrict__ W,
                                            int v_base, int k0, int tid) {
    #pragma unroll
    for (int i = 0; i < 8; i++) {
        int idx = tid + i * 256;
        int row = idx >> 3, c16 = idx & 7;
        uint32_t boff = (uint32_t)row * 128u + (uint32_t)c16 * 16u;
        const void* g = W + (size_t)(v_base + row) * cfg::H + k0 + c16 * 8;
        CP_ASYNC16(smem_abs + sw128(boff), g);
    }
}

__device__ __forceinline__ void load_afrag(uint32_t af[4][4], uint32_t aB,
                                           int a_row, int a_hi, int s) {
    #pragma unroll
    for (int mt = 0; mt < 4; mt++)
        ldsm4(af[mt], aB + sw128((uint32_t)(a_row + mt * 16) * 128u + s * 32 + a_hi));
}

__device__ __forceinline__ void load_bfrag(uint32_t bf[4][4], uint32_t bB,
                                           int b_row, int b_hi, int s) {
    #pragma unroll
    for (int ntt = 0; ntt < 4; ntt++)
        ldsm4(bf[ntt], bB + sw128((uint32_t)(b_row + ntt * 16) * 128u + s * 32 + b_hi));
}

__global__ void __launch_bounds__(256) k_lse() {
    extern __shared__ char smem[];
    const uint32_t sb = smem_u32(smem);
    const int tid  = threadIdx.x;
    const int lane = tid & 31;
    const int warp = tid >> 5;
    const int wm = warp & 1;          // 2 M-warps x 64
    const int wn = warp >> 1;         // 4 N-warps x 64
    const int g = blockIdx.z;
    const int m_base = blockIdx.x * cfg::BM;
    const int v_base = blockIdx.y * cfg::BN;
    const __nv_bfloat16* X = g_xb[g];
    const __nv_bfloat16* W = g_wb[g];

    // ldmatrix lane address patterns
    const int a_row = wm * 64 + (lane & 15);          // + mt*16
    const int a_hi  = (lane >> 4) * 16;               // 0 / 16 byte chunk
    const int b_row = wn * 64 + (lane & 7) + ((lane >> 4) << 3);  // + ntt*16
    const int b_hi  = ((lane >> 3) & 1) * 16;

    float c[4][8][4];
    #pragma unroll
    for (int mt = 0; mt < 4; mt++)
        #pragma unroll
        for (int nt = 0; nt < 8; nt++)
            #pragma unroll
            for (int j = 0; j < 4; j++) c[mt][nt][j] = 0.f;

    // Prologue: fill STAGES-1 = 3 stages (groups 0,1,2)
    #pragma unroll
    for (int s = 0; s < cfg::STAGES - 1; s++) {
        load_tile_A(sb + s * cfg::STG, X, m_base, s * cfg::BK, tid);
        load_tile_B(sb + s * cfg::STG + cfg::ASZ, W, v_base, s * cfg::BK, tid);
        CP_COMMIT();
    }

    for (int kb = 0; kb < cfg::KITERS; ++kb) {
        // One group committed per iter (possibly empty) -> uniform wait:
        // committed-before-wait = 3 + kb; <=2 pending => groups <= kb done.
        CP_WAIT2();
        __syncthreads();   // visibility of stage kb to all threads + all warps
                           // done computing stage kb-1 (the prefetch target)

        if (kb + cfg::STAGES - 1 < cfg::KITERS) {
            const int ks = kb + cfg::STAGES - 1;           // data kb+3
            const uint32_t ns = sb + (ks & 3) * cfg::STG;  // buffer (kb-1)%4
            load_tile_A(ns, X, m_base, ks * cfg::BK, tid);
            load_tile_B(ns + cfg::ASZ, W, v_base, ks * cfg::BK, tid);
        }
        CP_COMMIT();

        const uint32_t stg = sb + (kb & 3) * cfg::STG;
        const uint32_t aB = stg, bB = stg + cfg::ASZ;

        // 4 x k16 within BK=64, fragments double-buffered across s
        uint32_t af[2][4][4], bf[2][4][4];
        load_afrag(af[0], aB, a_row, a_hi, 0);
        load_bfrag(bf[0], bB, b_row, b_hi, 0);
        #pragma unroll
        for (int s = 0; s < 4; s++) {
            const int cur = s & 1, nxt = cur ^ 1;
            if (s < 3) {
                load_afrag(af[nxt], aB, a_row, a_hi, s + 1);
                load_bfrag(bf[nxt], bB, b_row, b_hi, s + 1);
            }
            #pragma unroll
            for (int mt = 0; mt < 4; mt++)
                #pragma unroll
                for (int nt = 0; nt < 8; nt++)
                    mma16816(c[mt][nt], af[cur][mt],
                             bf[cur][nt >> 1][(nt & 1) * 2],
                             bf[cur][nt >> 1][(nt & 1) * 2 + 1]);
        }
    }

    // ---- Epilogue: per-row online (max, sumexp) ----
    // Scratch aliases stage 0 (dead: last written for data kb=28 at iter 25,
    // last read at iter 28; barrier skew <=1 iter keeps all warps >= kb 30).
    float2* sepi = (float2*)(smem);   // [4 wn][128 rows]
    #pragma unroll
    for (int mt = 0; mt < 4; mt++) {
        #pragma unroll
        for (int h = 0; h < 2; h++) {                // row lo (regs 0,1) / hi (2,3)
            float mx = c[mt][0][2 * h];
            #pragma unroll
            for (int nt = 0; nt < 8; nt++) {
                mx = fmaxf(mx, c[mt][nt][2 * h]);
                mx = fmaxf(mx, c[mt][nt][2 * h + 1]);
            }
            float sum = 0.f;
            #pragma unroll
            for (int nt = 0; nt < 8; nt++) {
                sum += __expf(c[mt][nt][2 * h] - mx);
                sum += __expf(c[mt][nt][2 * h + 1] - mx);
            }
            // quad combine (threads lane^1, lane^2 share the same row)
            #pragma unroll
            for (int off = 1; off <= 2; off <<= 1) {
                float om = __shfl_xor_sync(0xffffffffu, mx, off);
                float ol = __shfl_xor_sync(0xffffffffu, sum, off);
                float nm = fmaxf(mx, om);
                sum = sum * __expf(mx - nm) + ol * __expf(om - nm);
                mx = nm;
            }
            if ((lane & 3) == 0) {
                int row = wm * 64 + mt * 16 + (lane >> 2) + 8 * h;
                sepi[wn * cfg::BM + row] = make_float2(mx, sum);
            }
        }
    }
    __syncthreads();

    if (tid < cfg::BM) {
        float2 p0 = sepi[0 * cfg::BM + tid];
        float mx = p0.x, L = p0.y;
        #pragma unroll
        for (int w = 1; w < 4; w++) {
            float2 p = sepi[w * cfg::BM + tid];
            float nm = fmaxf(mx, p.x);
            L = L * __expf(mx - nm) + p.y * __expf(p.x - nm);
            mx = nm;
        }
        const int gm = m_base + tid;
        const size_t base = ((size_t)(g * cfg::NCHUNK + blockIdx.y) * 2) * cfg::M;
        g_part[base + gm] = mx;
        g_part[base + cfg::M + gm] = L;
    }
}

// ============================================================================
// Kernel 4: merge chunk partials -> per-token loss -> block partial sums
// ============================================================================
__global__ void k_finalize(const float* __restrict__ adv, const int* __restrict__ amask) {
    const int m = blockIdx.x * blockDim.x + threadIdx.x;  // 8 x 256 = 2048
    const float NEG_INF = __int_as_float(0xff800000u);
    float lp[2];
    #pragma unroll
    for (int g = 0; g < 2; ++g) {
        float mx = NEG_INF;
        #pragma unroll 1
        for (int c = 0; c < cfg::NCHUNK; ++c) {
            mx = fmaxf(mx, g_part[((size_t)(g * cfg::NCHUNK + c) * 2) * cfg::M + m]);
        }
        float L = 0.f;
        #pragma unroll 1
        for (int c = 0; c < cfg::NCHUNK; ++c) {
            const size_t base = ((size_t)(g * cfg::NCHUNK + c) * 2) * cfg::M;
            L += g_part[base + cfg::M + m] * __expf(g_part[base + m] - mx);
        }
        lp[g] = g_seldot[g * cfg::M + m] - (mx + logf(L));
    }
    // coef1 = coef2 = 1 exactly -> per-token policy loss = -adv[b]
    const float d  = lp[1] - lp[0];            // ref_logps - logps
    const float kl = expf(d) - d - 1.0f;
    const float mk = (float)amask[m];
    const int b = m / cfg::T;
    const float lt = (-adv[b] + cfg::BETA * kl) * mk;

    __shared__ float sl[256], sm_[256];
    sl[threadIdx.x] = lt;
    sm_[threadIdx.x] = mk;
    __syncthreads();
    for (int o = 128; o; o >>= 1) {
        if (threadIdx.x < o) {
            sl[threadIdx.x] += sl[threadIdx.x + o];
            sm_[threadIdx.x] += sm_[threadIdx.x + o];
        }
        __syncthreads();
    }
    if (threadIdx.x == 0) {
        g_bsum[blockIdx.x] = sl[0];
        g_bsum[8 + blockIdx.x] = sm_[0];
    }
}

__global__ void k_writeout(float* out) {
    if (threadIdx.x == 0) {
        float L = 0.f, Mk = 0.f;
        for (int i = 0; i < 8; i++) { L += g_bsum[i]; Mk += g_bsum[8 + i]; }
        out[0] = L / fmaxf(Mk, 1.0f);
    }
}

// ============================================================================
// Launch
// ============================================================================
extern "C" void kernel_launch(void* const* d_in, const int* in_sizes, int n_in,
                              void* d_out, int out_size) {
    (void)in_sizes; (void)n_in; (void)out_size;
    const float* x   = (const float*)d_in[0];
    const float* lw  = (const float*)d_in[1];
    const float* rx  = (const float*)d_in[2];
    const float* rw  = (const float*)d_in[3];
    const float* adv = (const float*)d_in[4];
    const int*   ids = (const int*)d_in[5];
    const int*   am  = (const int*)d_in[6];

    const long long wh4 = (long long)cfg::V * cfg::H / 4;
    const long long xh4 = (long long)cfg::M * cfg::H / 4;
    k_convert<<<2048, 256>>>((const float4*)lw, 0, wh4);
    k_convert<<<2048, 256>>>((const float4*)rw, 1, wh4);
    k_convert<<<256, 256>>>((const float4*)x,  2, xh4);
    k_convert<<<256, 256>>>((const float4*)rx, 3, xh4);

    k_seldot<<<512, 256>>>(x, lw, rx, rw, ids);

    cudaFuncSetAttribute(k_lse, cudaFuncAttributeMaxDynamicSharedMemorySize, cfg::SMEM_TOTAL);
    dim3 grid(cfg::M / cfg::BM, cfg::NCHUNK, 2);   // (16, 125, 2)
    k_lse<<<grid, 256, cfg::SMEM_TOTAL>>>();

    k_finalize<<<cfg::M / 256, 256>>>(adv, am);
    k_writeout<<<1, 32>>>((float*)d_out);
}

// round 16
// speedup vs baseline: 1.1108x; 1.0342x over previous
#include <cuda_runtime.h>
#include <cuda_bf16.h>
#include <cstdint>
#include <cstddef>

// ============================================================================
// Problem constants
// ============================================================================
namespace cfg {
constexpr int B = 4, T = 512, H = 2048, V = 32000;
constexpr int M = B * T;                 // 2048 tokens
constexpr float BETA = 0.1f;

// GEMM tiling (mma.sync path — tcgen05 rejected by this toolchain's
// compute_103 family target)
constexpr int BM = 128;                  // CTA M tile
constexpr int BN = 256;                  // CTA N tile
constexpr int BK = 64;                   // K block (64 bf16 = 128B = SW128 atom row)
constexpr int KITERS = H / BK;           // 32
constexpr int STAGES = 4;
constexpr int NCHUNK = V / BN;           // 125
static_assert(NCHUNK * BN == V, "vocab tiling");

constexpr int THREADS = 512;             // 16 warps: 4(M) x 4(N), warp tile 32x64

// SMEM: per stage A(128x128B)=16KB + B(256x128B)=32KB; 4 stages = 192KB.
// Epilogue scratch (4KB) aliases stage 0 (dead after the last iters).
constexpr int ASZ = BM * 128;            // 16384
constexpr int BSZ = BN * 128;            // 32768
constexpr int STG = ASZ + BSZ;           // 49152
constexpr int SMEM_TOTAL = STAGES * STG; // 196608
}  // namespace cfg

// ============================================================================
// Persistent device scratch (no runtime allocation allowed)
// ============================================================================
__device__ __nv_bfloat16 g_wb[2][(size_t)cfg::V * cfg::H];   // bf16 weights
__device__ __nv_bfloat16 g_xb[2][(size_t)cfg::M * cfg::H];   // bf16 activations
__device__ float g_seldot[2 * cfg::M];                       // exact fp32 selected logits
__device__ float g_part[2 * cfg::NCHUNK * 2 * cfg::M];       // per-chunk (max, sumexp)
__device__ float g_bsum[16];                                 // block partial sums

// ============================================================================
// PTX helpers
// ============================================================================
__device__ __forceinline__ uint32_t smem_u32(const void* p) {
    uint32_t a;
    asm("{ .reg .u64 t; cvta.to.shared.u64 t, %1; cvt.u32.u64 %0, t; }"
        : "=r"(a) : "l"(p));
    return a;
}

#define CP_ASYNC16(dst_u32, src_ptr) \
    asm volatile("cp.async.cg.shared.global [%0], [%1], 16;" \
                 :: "r"(dst_u32), "l"(src_ptr) : "memory")
#define CP_COMMIT() asm volatile("cp.async.commit_group;" ::: "memory")
#define CP_WAIT2()  asm volatile("cp.async.wait_group 2;" ::: "memory")

__device__ __forceinline__ uint32_t sw128(uint32_t off) {
    return off ^ ((off >> 3) & 0x70);
}

__device__ __forceinline__ void ldsm4(uint32_t* r, uint32_t addr) {
    asm volatile("ldmatrix.sync.aligned.m8n8.x4.shared.b16 {%0,%1,%2,%3}, [%4];"
                 : "=r"(r[0]), "=r"(r[1]), "=r"(r[2]), "=r"(r[3]) : "r"(addr));
}

__device__ __forceinline__ void mma16816(float* c, const uint32_t* a,
                                         uint32_t b0, uint32_t b1) {
    asm volatile(
        "mma.sync.aligned.m16n8k16.row.col.f32.bf16.bf16.f32 "
        "{%0,%1,%2,%3}, {%4,%5,%6,%7}, {%8,%9}, {%0,%1,%2,%3};"
        : "+f"(c[0]), "+f"(c[1]), "+f"(c[2]), "+f"(c[3])
        : "r"(a[0]), "r"(a[1]), "r"(a[2]), "r"(a[3]), "r"(b0), "r"(b1));
}

// ============================================================================
// Kernel 1: fp32 -> bf16 conversion
// ============================================================================
__global__ void k_convert(const float4* __restrict__ src, int target, long long n4) {
    __nv_bfloat162* dst =
        target == 0 ? (__nv_bfloat162*)g_wb[0] :
        target == 1 ? (__nv_bfloat162*)g_wb[1] :
        target == 2 ? (__nv_bfloat162*)g_xb[0] : (__nv_bfloat162*)g_xb[1];
    long long stride = (long long)gridDim.x * blockDim.x;
    for (long long i = (long long)blockIdx.x * blockDim.x + threadIdx.x; i < n4; i += stride) {
        float4 v = src[i];
        dst[2 * i]     = __float22bfloat162_rn(make_float2(v.x, v.y));
        dst[2 * i + 1] = __float22bfloat162_rn(make_float2(v.z, v.w));
    }
}

// ============================================================================
// Kernel 2: exact fp32 selected-token logits (one warp per (gemm, token))
// ============================================================================
__global__ void k_seldot(const float* __restrict__ x0, const float* __restrict__ w0,
                         const float* __restrict__ x1, const float* __restrict__ w1,
                         const int* __restrict__ ids) {
    int wglob = (blockIdx.x * blockDim.x + threadIdx.x) >> 5;
    int lane  = threadIdx.x & 31;
    int g = wglob >> 11;          // /2048
    int m = wglob & (cfg::M - 1);
    if (g >= 2) return;
    const float* x = g ? x1 : x0;
    const float* w = g ? w1 : w0;
    int sel = ids[m];
    const float* xr = x + (size_t)m * cfg::H;
    const float* wr = w + (size_t)sel * cfg::H;
    float acc = 0.f;
    #pragma unroll 8
    for (int k = lane; k < cfg::H; k += 32) acc = fmaf(xr[k], wr[k], acc);
    #pragma unroll
    for (int o = 16; o; o >>= 1) acc += __shfl_xor_sync(0xffffffffu, acc, o);
    if (lane == 0) g_seldot[g * cfg::M + m] = acc;
}

// ============================================================================
// Kernel 3: bf16 mma.sync GEMM + streaming logsumexp partials
//   grid = (16 m-tiles, 125 v-chunks, 2 gemms), 512 threads (16 warps)
//   warp grid 4(M) x 4(N), warp tile 32x64 — 4 warps/SMSP hide latency
//   Single-barrier 4-stage cp.async pipeline, single-buffered fragments.
// ============================================================================
__device__ __forceinline__ void load_tile_A(uint32_t smem_abs, const __nv_bfloat16* __restrict__ X,
                                            int m_base, int k0, int tid) {
    // 128 rows x 128B, 1024 x 16B chunks, 512 threads -> 2 iters
    #pragma unroll
    for (int i = 0; i < 2; i++) {
        int idx = tid + i * cfg::THREADS;
        int row = idx >> 3, c16 = idx & 7;
        uint32_t boff = (uint32_t)row * 128u + (uint32_t)c16 * 16u;
        const void* g = X + (size_t)(m_base + row) * cfg::H + k0 + c16 * 8;
        CP_ASYNC16(smem_abs + sw128(boff), g);
    }
}

__device__ __forceinline__ void load_tile_B(uint32_t smem_abs, const __nv_bfloat16* __restrict__ W,
                                            int v_base, int k0, int tid) {
    // 256 rows x 128B, 2048 x 16B chunks, 512 threads -> 4 iters
    #pragma unroll
    for (int i = 0; i < 4; i++) {
        int idx = tid + i * cfg::THREADS;
        int row = idx >> 3, c16 = idx & 7;
        uint32_t boff = (uint32_t)row * 128u + (uint32_t)c16 * 16u;
        const void* g = W + (size_t)(v_base + row) * cfg::H + k0 + c16 * 8;
        CP_ASYNC16(smem_abs + sw128(boff), g);
    }
}

__global__ void __launch_bounds__(cfg::THREADS, 1) k_lse() {
    extern __shared__ char smem[];
    const uint32_t sb = smem_u32(smem);
    const int tid  = threadIdx.x;
    const int lane = tid & 31;
    const int warp = tid >> 5;
    const int wm = warp >> 2;         // 4 M-warps x 32 rows
    const int wn = warp & 3;          // 4 N-warps x 64 cols
    const int g = blockIdx.z;
    const int m_base = blockIdx.x * cfg::BM;
    const int v_base = blockIdx.y * cfg::BN;
    const __nv_bfloat16* X = g_xb[g];
    const __nv_bfloat16* W = g_wb[g];

    // ldmatrix lane address patterns
    const int a_row = wm * 32 + (lane & 15);          // + mt*16
    const int a_hi  = (lane >> 4) * 16;               // 0 / 16 byte chunk
    const int b_row = wn * 64 + (lane & 7) + ((lane >> 4) << 3);  // + ntt*16
    const int b_hi  = ((lane >> 3) & 1) * 16;

    float c[2][8][4];
    #pragma unroll
    for (int mt = 0; mt < 2; mt++)
        #pragma unroll
        for (int nt = 0; nt < 8; nt++)
            #pragma unroll
            for (int j = 0; j < 4; j++) c[mt][nt][j] = 0.f;

    // Prologue: fill STAGES-1 = 3 stages (groups 0,1,2)
    #pragma unroll
    for (int s = 0; s < cfg::STAGES - 1; s++) {
        load_tile_A(sb + s * cfg::STG, X, m_base, s * cfg::BK, tid);
        load_tile_B(sb + s * cfg::STG + cfg::ASZ, W, v_base, s * cfg::BK, tid);
        CP_COMMIT();
    }

    for (int kb = 0; kb < cfg::KITERS; ++kb) {
        // One group committed per iter (possibly empty) -> uniform wait:
        // committed-before-wait = 3 + kb; <=2 pending => groups <= kb done.
        CP_WAIT2();
        __syncthreads();   // stage kb visible to all; all warps done with the
                           // prefetch-target buffer (kb-1)%4

        if (kb + cfg::STAGES - 1 < cfg::KITERS) {
            const int ks = kb + cfg::STAGES - 1;           // data kb+3
            const uint32_t ns = sb + (ks & 3) * cfg::STG;  // buffer (kb-1)%4
            load_tile_A(ns, X, m_base, ks * cfg::BK, tid);
            load_tile_B(ns + cfg::ASZ, W, v_base, ks * cfg::BK, tid);
        }
        CP_COMMIT();

        const uint32_t stg = sb + (kb & 3) * cfg::STG;
        const uint32_t aB = stg, bB = stg + cfg::ASZ;

        // 4 x k16 within BK=64; single-buffered fragments, latency hidden by
        // 4 warps per scheduler
        #pragma unroll
        for (int s = 0; s < 4; s++) {
            uint32_t af[2][4], bf[4][4];
            #pragma unroll
            for (int mt = 0; mt < 2; mt++)
                ldsm4(af[mt], aB + sw128((uint32_t)(a_row + mt * 16) * 128u + s * 32 + a_hi));
            #pragma unroll
            for (int ntt = 0; ntt < 4; ntt++)
                ldsm4(bf[ntt], bB + sw128((uint32_t)(b_row + ntt * 16) * 128u + s * 32 + b_hi));
            #pragma unroll
            for (int mt = 0; mt < 2; mt++)
                #pragma unroll
                for (int nt = 0; nt < 8; nt++)
                    mma16816(c[mt][nt], af[mt],
                             bf[nt >> 1][(nt & 1) * 2],
                             bf[nt >> 1][(nt & 1) * 2 + 1]);
        }
    }

    // ---- Epilogue: per-row online (max, sumexp) ----
    // Scratch aliases stage 0 (dead by the final iterations).
    float2* sepi = (float2*)(smem);   // [4 wn][128 rows]
    #pragma unroll
    for (int mt = 0; mt < 2; mt++) {
        #pragma unroll
        for (int h = 0; h < 2; h++) {                // row lo (regs 0,1) / hi (2,3)
            float mx = c[mt][0][2 * h];
            #pragma unroll
            for (int nt = 0; nt < 8; nt++) {
                mx = fmaxf(mx, c[mt][nt][2 * h]);
                mx = fmaxf(mx, c[mt][nt][2 * h + 1]);
            }
            float sum = 0.f;
            #pragma unroll
            for (int nt = 0; nt < 8; nt++) {
                sum += __expf(c[mt][nt][2 * h] - mx);
                sum += __expf(c[mt][nt][2 * h + 1] - mx);
            }
            // quad combine (threads lane^1, lane^2 share the same row)
            #pragma unroll
            for (int off = 1; off <= 2; off <<= 1) {
                float om = __shfl_xor_sync(0xffffffffu, mx, off);
                float ol = __shfl_xor_sync(0xffffffffu, sum, off);
                float nm = fmaxf(mx, om);
                sum = sum * __expf(mx - nm) + ol * __expf(om - nm);
                mx = nm;
            }
            if ((lane & 3) == 0) {
                int row = wm * 32 + mt * 16 + (lane >> 2) + 8 * h;
                sepi[wn * cfg::BM + row] = make_float2(mx, sum);
            }
        }
    }
    __syncthreads();

    if (tid < cfg::BM) {
        float2 p0 = sepi[0 * cfg::BM + tid];
        float mx = p0.x, L = p0.y;
        #pragma unroll
        for (int w = 1; w < 4; w++) {
            float2 p = sepi[w * cfg::BM + tid];
            float nm = fmaxf(mx, p.x);
            L = L * __expf(mx - nm) + p.y * __expf(p.x - nm);
            mx = nm;
        }
        const int gm = m_base + tid;
        const size_t base = ((size_t)(g * cfg::NCHUNK + blockIdx.y) * 2) * cfg::M;
        g_part[base + gm] = mx;
        g_part[base + cfg::M + gm] = L;
    }
}

// ============================================================================
// Kernel 4: merge chunk partials -> per-token loss -> block partial sums
// ============================================================================
__global__ void k_finalize(const float* __restrict__ adv, const int* __restrict__ amask) {
    const int m = blockIdx.x * blockDim.x + threadIdx.x;  // 8 x 256 = 2048
    const float NEG_INF = __int_as_float(0xff800000u);
    float lp[2];
    #pragma unroll
    for (int g = 0; g < 2; ++g) {
        float mx = NEG_INF;
        #pragma unroll 1
        for (int c = 0; c < cfg::NCHUNK; ++c) {
            mx = fmaxf(mx, g_part[((size_t)(g * cfg::NCHUNK + c) * 2) * cfg::M + m]);
        }
        float L = 0.f;
        #pragma unroll 1
        for (int c = 0; c < cfg::NCHUNK; ++c) {
            const size_t base = ((size_t)(g * cfg::NCHUNK + c) * 2) * cfg::M;
            L += g_part[base + cfg::M + m] * __expf(g_part[base + m] - mx);
        }
        lp[g] = g_seldot[g * cfg::M + m] - (mx + logf(L));
    }
    // coef1 = coef2 = 1 exactly -> per-token policy loss = -adv[b]
    const float d  = lp[1] - lp[0];            // ref_logps - logps
    const float kl = expf(d) - d - 1.0f;
    const float mk = (float)amask[m];
    const int b = m / cfg::T;
    const float lt = (-adv[b] + cfg::BETA * kl) * mk;

    __shared__ float sl[256], sm_[256];
    sl[threadIdx.x] = lt;
    sm_[threadIdx.x] = mk;
    __syncthreads();
    for (int o = 128; o; o >>= 1) {
        if (threadIdx.x < o) {
            sl[threadIdx.x] += sl[threadIdx.x + o];
            sm_[threadIdx.x] += sm_[threadIdx.x + o];
        }
        __syncthreads();
    }
    if (threadIdx.x == 0) {
        g_bsum[blockIdx.x] = sl[0];
        g_bsum[8 + blockIdx.x] = sm_[0];
    }
}

__global__ void k_writeout(float* out) {
    if (threadIdx.x == 0) {
        float L = 0.f, Mk = 0.f;
        for (int i = 0; i < 8; i++) { L += g_bsum[i]; Mk += g_bsum[8 + i]; }
        out[0] = L / fmaxf(Mk, 1.0f);
    }
}

// ============================================================================
// Launch
// ============================================================================
extern "C" void kernel_launch(void* const* d_in, const int* in_sizes, int n_in,
                              void* d_out, int out_size) {
    (void)in_sizes; (void)n_in; (void)out_size;
    const float* x   = (const float*)d_in[0];
    const float* lw  = (const float*)d_in[1];
    const float* rx  = (const float*)d_in[2];
    const float* rw  = (const float*)d_in[3];
    const float* adv = (const float*)d_in[4];
    const int*   ids = (const int*)d_in[5];
    const int*   am  = (const int*)d_in[6];

    const long long wh4 = (long long)cfg::V * cfg::H / 4;
    const long long xh4 = (long long)cfg::M * cfg::H / 4;
    k_convert<<<3072, 256>>>((const float4*)lw, 0, wh4);
    k_convert<<<3072, 256>>>((const float4*)rw, 1, wh4);
    k_convert<<<256, 256>>>((const float4*)x,  2, xh4);
    k_convert<<<256, 256>>>((const float4*)rx, 3, xh4);

    k_seldot<<<512, 256>>>(x, lw, rx, rw, ids);

    cudaFuncSetAttribute(k_lse, cudaFuncAttributeMaxDynamicSharedMemorySize, cfg::SMEM_TOTAL);
    dim3 grid(cfg::M / cfg::BM, cfg::NCHUNK, 2);   // (16, 125, 2)
    k_lse<<<grid, cfg::THREADS, cfg::SMEM_TOTAL>>>();

    k_finalize<<<cfg::M / 256, 256>>>(adv, am);
    k_writeout<<<1, 32>>>((float*)d_out);
}